// round 13
// baseline (speedup 1.0000x reference)
#include <cuda_runtime.h>
#include <math.h>

// IDM_43748536877069  — B=8, NV=2048 pairwise IDM leader search + epilogue.
//
// Rotated-frame cone test (exact equivalence):
//   u = dx*cos(psi_j) + dy*sin(psi_j)    (longitudinal)
//   w = -dx*sin(psi_j) + dy*cos(psi_j)   (lateral)
//   cone ⟺ |w|*cot(20°) < u             (implies u>0; dx=dy=0 -> false)
// dx,dy computed explicitly so the self-pair is exactly (0,0) -> never leader.
//
// R13: R4 main loop (proven fastest) + warp-shuffle combine. The 8 sub-
// partials of an ego occupy 8 consecutive lanes of one warp, so a 3-round
// shfl.xor butterfly replaces the smem partials + __syncthreads + serial
// 112-thread epilogue; the IDM epilogue runs on lane sub==0 of every 8-lane
// group (8x the epilogue parallelism, one less barrier, -7KB smem).

#define NV 2048
#define SLOTS 112                      // egos per block
#define SUBS 8                         // candidate-split per ego
#define THREADS (SLOTS * SUBS)         // 896
#define PAIRS (NV / 2)                 // 1024 float4-packed candidate pairs
#define PCHUNK (PAIRS / SUBS)          // 128 pairs per thread
#define BPB ((NV + SLOTS - 1) / SLOTS) // 19 blocks per batch

__global__ __launch_bounds__(THREADS, 1)
void idm_kernel(const float* __restrict__ state,
                const float* __restrict__ lengths,
                const float* __restrict__ v0p,
                const float* __restrict__ s0p,
                const float* __restrict__ dthp,
                const float* __restrict__ amaxp,
                const float* __restrict__ bp,
                float* __restrict__ out)
{
    __shared__ float4 xy4[PAIRS];            // 16 KB: (x0,y0,x1,y1) per pair

    const int b       = blockIdx.x / BPB;
    const int egoBase = (blockIdx.x % BPB) * SLOTS;
    const float* st   = state + (size_t)b * NV * 5;

    // Stage candidate positions, packed two per float4.
    for (int p = threadIdx.x; p < PAIRS; p += THREADS) {
        const float* a = st + (2 * p) * 5;
        xy4[p] = make_float4(a[0], a[1], a[5], a[6]);
    }
    __syncthreads();

    // lane mapping: sub = tid&7, ego slot e = tid>>3.
    // A warp = 4 egos x 8 subs; loop loads xy4[8t+sub] -> 8 consecutive
    // float4 smem addresses per warp (128B, conflict-free, 4-lane broadcast).
    const int sub = threadIdx.x & 7;
    const int e   = threadIdx.x >> 3;
    const int j   = egoBase + e;
    const bool valid = (j < NV);
    const int jc  = valid ? j : 0;

    const float4 cj0 = xy4[jc >> 1];
    const float xj = (jc & 1) ? cj0.z : cj0.x;
    const float yj = (jc & 1) ? cj0.w : cj0.y;
    const float psj = __ldg(st + jc * 5 + 3);
    float sj, cjv;
    sincosf(psj, &sj, &cjv);

    const float COT20 = 2.7474774194546225f;   // 1/tan(20 deg)
    const float scj = cjv * COT20;
    const float nsj = -sj * COT20;

    float best = __int_as_float(0x7f800000);   // +inf
    int   bi   = 0;

    if (valid) {
        #pragma unroll 4
        for (int t = 0; t < PCHUNK; ++t) {
            const int p = (t << 3) + sub;        // pair index, p ≡ sub (mod 8)
            const float4 c = xy4[p];

            // even candidate (i = 2p)
            const float dx0 = c.x - xj;
            const float dy0 = c.y - yj;
            const float u0  = fmaf(dx0, cjv, dy0 * sj);
            const float w0  = fmaf(dy0, scj, dx0 * nsj);
            // odd candidate (i = 2p+1)
            const float dx1 = c.z - xj;
            const float dy1 = c.w - yj;
            const float u1  = fmaf(dx1, cjv, dy1 * sj);
            const float w1  = fmaf(dy1, scj, dx1 * nsj);

            const bool ok0 = (fabsf(w0) < u0) && (u0 < best);
            best = ok0 ? u0 : best;
            bi   = ok0 ? (p << 1) : bi;
            const bool ok1 = (fabsf(w1) < u1) && (u1 < best);
            best = ok1 ? u1 : best;
            bi   = ok1 ? ((p << 1) | 1) : bi;
        }
    }

    // Combine the 8 sub-partials with a butterfly over the 8-lane group.
    // Lexicographic (value, index) min == order-independent first-index argmin.
    #pragma unroll
    for (int off = 4; off > 0; off >>= 1) {
        const float v2 = __shfl_xor_sync(0xffffffffu, best, off);
        const int   i2 = __shfl_xor_sync(0xffffffffu, bi,   off);
        if (v2 < best || (v2 == best && i2 < bi)) { best = v2; bi = i2; }
    }

    // IDM epilogue on lane sub==0 of each ego group (4 egos per warp).
    if (sub == 0 && valid) {
        const float v0   = v0p[0];
        const float s0   = s0p[0];
        const float dth  = dthp[0];
        const float amax = amaxp[0];
        const float bb   = bp[0];

        const float vje = __ldg(st + jc * 5 + 2);

        const float q  = vje / v0;
        const float q2 = q * q;
        const float afree = amax * (1.0f - q2 * q2);

        float action = afree;
        const float sal = best - lengths[jc];
        if (isfinite(sal)) {
            const float vl  = __ldg(st + bi * 5 + 2);
            const float psl = __ldg(st + bi * 5 + 3);
            float sl, cl;
            sincosf(psl, &sl, &cl);
            const float dvx = vl * cl - vje * cjv;
            const float dvy = vl * sl - vje * sj;
            const float ndv = fmaf(dvx, cjv, dvy * sj);

            const float sstar = s0 + vje * dth
                              + vje * ndv / (2.0f * sqrtf(amax * bb));
            const float r = sstar / sal;
            action = afree - amax * r * r;
        }
        out[(size_t)b * NV + jc] = action;
    }
}

extern "C" void kernel_launch(void* const* d_in, const int* in_sizes, int n_in,
                              void* d_out, int out_size) {
    const float* state   = (const float*)d_in[0];
    const float* lengths = (const float*)d_in[1];
    const float* v0      = (const float*)d_in[2];
    const float* s0      = (const float*)d_in[3];
    const float* dth     = (const float*)d_in[4];
    const float* amax    = (const float*)d_in[5];
    const float* bpar    = (const float*)d_in[6];
    float* out = (float*)d_out;

    const int B = in_sizes[0] / (NV * 5);
    const int grid = B * BPB;    // 8 * 19 = 152 == #SMs on GB300
    idm_kernel<<<grid, THREADS>>>(state, lengths, v0, s0, dth, amax, bpar, out);
}

// round 14
// speedup vs baseline: 1.0120x; 1.0120x over previous
#include <cuda_runtime.h>
#include <math.h>

// IDM_43748536877069  — B=8, NV=2048 pairwise IDM leader search + epilogue.
//
// Rotated-frame cone test (exact equivalence):
//   u = dx*cos(psi_j) + dy*sin(psi_j)    (longitudinal)
//   w = -dx*sin(psi_j) + dy*cos(psi_j)   (lateral)
//   cone ⟺ |w|*cot(20°) < u             (implies u>0; dx=dy=0 -> false)
// dx,dy computed explicitly so the self-pair is exactly (0,0) -> never leader.
//
// R14 = R7 main loop (unroll 8) + R13 shuffle combine, plus tail-latency
// elimination: (v,psi) staged in smem so the bi-dependent leader lookup is an
// LDS (29cyc) not a tail LDG (~600cyc); scalar params and lengths[j] hoisted
// before the main loop so their latency hides behind 128 iterations.

#define NV 2048
#define SLOTS 112                      // egos per block
#define SUBS 8                         // candidate-split per ego
#define THREADS (SLOTS * SUBS)         // 896
#define PAIRS (NV / 2)                 // 1024 float4-packed candidate pairs
#define PCHUNK (PAIRS / SUBS)          // 128 pairs per thread
#define BPB ((NV + SLOTS - 1) / SLOTS) // 19 blocks per batch

__global__ __launch_bounds__(THREADS, 1)
void idm_kernel(const float* __restrict__ state,
                const float* __restrict__ lengths,
                const float* __restrict__ v0p,
                const float* __restrict__ s0p,
                const float* __restrict__ dthp,
                const float* __restrict__ amaxp,
                const float* __restrict__ bp,
                float* __restrict__ out)
{
    __shared__ float4 xy4[PAIRS];            // 16 KB: (x0,y0,x1,y1) per pair
    __shared__ float4 vp4[PAIRS];            // 16 KB: (v0,psi0,v1,psi1) per pair

    const int b       = blockIdx.x / BPB;
    const int egoBase = (blockIdx.x % BPB) * SLOTS;
    const float* st   = state + (size_t)b * NV * 5;

    // Stage candidate positions and (v,psi), packed two vehicles per float4.
    for (int p = threadIdx.x; p < PAIRS; p += THREADS) {
        const float* a = st + (2 * p) * 5;
        xy4[p] = make_float4(a[0], a[1], a[5], a[6]);
        vp4[p] = make_float4(a[2], a[3], a[7], a[8]);
    }
    __syncthreads();

    // lane mapping: sub = tid&7, ego slot e = tid>>3.
    // A warp = 4 egos x 8 subs; loop loads xy4[8t+sub] -> 8 consecutive
    // float4 smem addresses per warp (128B, conflict-free, 4-lane broadcast).
    const int sub = threadIdx.x & 7;
    const int e   = threadIdx.x >> 3;
    const int j   = egoBase + e;
    const bool valid = (j < NV);
    const int jc  = valid ? j : 0;

    const float4 cj0 = xy4[jc >> 1];
    const float xj = (jc & 1) ? cj0.z : cj0.x;
    const float yj = (jc & 1) ? cj0.w : cj0.y;
    const float4 ej = vp4[jc >> 1];
    const float vje = (jc & 1) ? ej.z : ej.x;
    const float psj = (jc & 1) ? ej.w : ej.y;
    float sj, cjv;
    sincosf(psj, &sj, &cjv);

    // Hoisted scalar/parameter loads — latency hidden behind the main loop.
    const float v0   = __ldg(v0p);
    const float s0   = __ldg(s0p);
    const float dth  = __ldg(dthp);
    const float amax = __ldg(amaxp);
    const float bb   = __ldg(bp);
    const float lenj = __ldg(lengths + jc);

    const float COT20 = 2.7474774194546225f;   // 1/tan(20 deg)
    const float scj = cjv * COT20;
    const float nsj = -sj * COT20;

    float best = __int_as_float(0x7f800000);   // +inf
    int   bi   = 0;

    if (valid) {
        #pragma unroll 8
        for (int t = 0; t < PCHUNK; ++t) {
            const int p = (t << 3) + sub;        // pair index, p ≡ sub (mod 8)
            const float4 c = xy4[p];

            // even candidate (i = 2p)
            const float dx0 = c.x - xj;
            const float dy0 = c.y - yj;
            const float u0  = fmaf(dx0, cjv, dy0 * sj);
            const float w0  = fmaf(dy0, scj, dx0 * nsj);
            // odd candidate (i = 2p+1)
            const float dx1 = c.z - xj;
            const float dy1 = c.w - yj;
            const float u1  = fmaf(dx1, cjv, dy1 * sj);
            const float w1  = fmaf(dy1, scj, dx1 * nsj);

            const bool ok0 = (fabsf(w0) < u0) && (u0 < best);
            best = ok0 ? u0 : best;
            bi   = ok0 ? (p << 1) : bi;
            const bool ok1 = (fabsf(w1) < u1) && (u1 < best);
            best = ok1 ? u1 : best;
            bi   = ok1 ? ((p << 1) | 1) : bi;
        }
    }

    // Combine the 8 sub-partials with a butterfly over the 8-lane group.
    // Lexicographic (value, index) min == order-independent first-index argmin.
    #pragma unroll
    for (int off = 4; off > 0; off >>= 1) {
        const float v2 = __shfl_xor_sync(0xffffffffu, best, off);
        const int   i2 = __shfl_xor_sync(0xffffffffu, bi,   off);
        if (v2 < best || (v2 == best && i2 < bi)) { best = v2; bi = i2; }
    }

    // IDM epilogue on lane sub==0 of each ego group (4 egos per warp).
    if (sub == 0 && valid) {
        const float q  = vje / v0;
        const float q2 = q * q;
        const float afree = amax * (1.0f - q2 * q2);

        float action = afree;
        const float sal = best - lenj;
        if (isfinite(sal)) {
            // leader kinematics from staged smem (LDS, not tail LDG)
            const float4 lp = vp4[bi >> 1];
            const float vl  = (bi & 1) ? lp.z : lp.x;
            const float psl = (bi & 1) ? lp.w : lp.y;
            float sl, cl;
            sincosf(psl, &sl, &cl);
            const float dvx = vl * cl - vje * cjv;
            const float dvy = vl * sl - vje * sj;
            const float ndv = fmaf(dvx, cjv, dvy * sj);

            const float sstar = s0 + vje * dth
                              + vje * ndv / (2.0f * sqrtf(amax * bb));
            const float r = sstar / sal;
            action = afree - amax * r * r;
        }
        out[(size_t)b * NV + jc] = action;
    }
}

extern "C" void kernel_launch(void* const* d_in, const int* in_sizes, int n_in,
                              void* d_out, int out_size) {
    const float* state   = (const float*)d_in[0];
    const float* lengths = (const float*)d_in[1];
    const float* v0      = (const float*)d_in[2];
    const float* s0      = (const float*)d_in[3];
    const float* dth     = (const float*)d_in[4];
    const float* amax    = (const float*)d_in[5];
    const float* bpar    = (const float*)d_in[6];
    float* out = (float*)d_out;

    const int B = in_sizes[0] / (NV * 5);
    const int grid = B * BPB;    // 8 * 19 = 152 == #SMs on GB300
    idm_kernel<<<grid, THREADS>>>(state, lengths, v0, s0, dth, amax, bpar, out);
}

// round 15
// speedup vs baseline: 1.0225x; 1.0104x over previous
#include <cuda_runtime.h>
#include <math.h>

// IDM_43748536877069  — B=8, NV=2048 pairwise IDM leader search + epilogue.
//
// Rotated-frame cone test (exact equivalence):
//   u = dx*cos(psi_j) + dy*sin(psi_j)    (longitudinal)
//   w = -dx*sin(psi_j) + dy*cos(psi_j)   (lateral)
//   cone ⟺ |w|*cot(20°) < u             (implies u>0; dx=dy=0 -> false)
// dx,dy computed explicitly so the self-pair is exactly (0,0) -> never leader.
//
// R15 (consolidation): R7 structure (best measured ncu: unroll 8, single
// accumulator, smem partial combine) + hoisted scalar/length loads so their
// global-load latency hides behind the 128-iteration main loop instead of
// the low-parallelism epilogue tail.

#define NV 2048
#define SLOTS 112                      // egos per block
#define SUBS 8                         // candidate-split per ego
#define THREADS (SLOTS * SUBS)         // 896
#define PAIRS (NV / 2)                 // 1024 float4-packed candidate pairs
#define PCHUNK (PAIRS / SUBS)          // 128 pairs per thread
#define BPB ((NV + SLOTS - 1) / SLOTS) // 19 blocks per batch

__global__ __launch_bounds__(THREADS, 1)
void idm_kernel(const float* __restrict__ state,
                const float* __restrict__ lengths,
                const float* __restrict__ v0p,
                const float* __restrict__ s0p,
                const float* __restrict__ dthp,
                const float* __restrict__ amaxp,
                const float* __restrict__ bp,
                float* __restrict__ out)
{
    __shared__ float4 xy4[PAIRS];            // 16 KB: (x0,y0,x1,y1) per pair
    __shared__ float  pval[SUBS][SLOTS];     // 3.5 KB
    __shared__ int    pidx[SUBS][SLOTS];     // 3.5 KB

    const int b       = blockIdx.x / BPB;
    const int egoBase = (blockIdx.x % BPB) * SLOTS;
    const float* st   = state + (size_t)b * NV * 5;

    // Stage candidate positions, packed two per float4.
    for (int p = threadIdx.x; p < PAIRS; p += THREADS) {
        const float* a = st + (2 * p) * 5;
        xy4[p] = make_float4(a[0], a[1], a[5], a[6]);
    }
    __syncthreads();

    // lane mapping: sub = tid&7, ego slot e = tid>>3.
    // A warp = 4 egos x 8 subs; loop loads xy4[8t+sub] -> 8 consecutive
    // float4 smem addresses per warp (128B, conflict-free, 4-lane broadcast).
    const int sub = threadIdx.x & 7;
    const int e   = threadIdx.x >> 3;
    const int j   = egoBase + e;
    const bool valid = (j < NV);
    const int jc  = valid ? j : 0;

    const float4 cj0 = xy4[jc >> 1];
    const float xj = (jc & 1) ? cj0.z : cj0.x;
    const float yj = (jc & 1) ? cj0.w : cj0.y;
    const float psj = __ldg(st + jc * 5 + 3);
    float sj, cjv;
    sincosf(psj, &sj, &cjv);

    // Hoisted parameter loads: latency hidden behind the main loop.
    const float v0   = __ldg(v0p);
    const float s0   = __ldg(s0p);
    const float dth  = __ldg(dthp);
    const float amax = __ldg(amaxp);
    const float bb   = __ldg(bp);
    const float lenj = __ldg(lengths + jc);
    const float vje  = __ldg(st + jc * 5 + 2);

    const float COT20 = 2.7474774194546225f;   // 1/tan(20 deg)
    const float scj = cjv * COT20;
    const float nsj = -sj * COT20;

    float best = __int_as_float(0x7f800000);   // +inf
    int   bi   = 0;

    if (valid) {
        #pragma unroll 8
        for (int t = 0; t < PCHUNK; ++t) {
            const int p = (t << 3) + sub;        // pair index, p ≡ sub (mod 8)
            const float4 c = xy4[p];

            // even candidate (i = 2p)
            const float dx0 = c.x - xj;
            const float dy0 = c.y - yj;
            const float u0  = fmaf(dx0, cjv, dy0 * sj);
            const float w0  = fmaf(dy0, scj, dx0 * nsj);
            // odd candidate (i = 2p+1)
            const float dx1 = c.z - xj;
            const float dy1 = c.w - yj;
            const float u1  = fmaf(dx1, cjv, dy1 * sj);
            const float w1  = fmaf(dy1, scj, dx1 * nsj);

            const bool ok0 = (fabsf(w0) < u0) && (u0 < best);
            best = ok0 ? u0 : best;
            bi   = ok0 ? (p << 1) : bi;
            const bool ok1 = (fabsf(w1) < u1) && (u1 < best);
            best = ok1 ? u1 : best;
            bi   = ok1 ? ((p << 1) | 1) : bi;
        }
    }
    pval[sub][e] = best;
    pidx[sub][e] = bi;
    __syncthreads();

    // One thread per ego: 8-way combine (tie -> lower index) + IDM epilogue.
    if (threadIdx.x < SLOTS) {
        const int ee = threadIdx.x;
        const int jj = egoBase + ee;
        if (jj < NV) {
            float fbv = pval[0][ee];
            int   fbx = pidx[0][ee];
            #pragma unroll
            for (int s = 1; s < SUBS; ++s) {
                const float v2 = pval[s][ee];
                const int   i2 = pidx[s][ee];
                if (v2 < fbv || (v2 == fbv && i2 < fbx)) { fbv = v2; fbx = i2; }
            }

            const float vje2  = __ldg(st + jj * 5 + 2);
            const float psje  = __ldg(st + jj * 5 + 3);
            float sje, cje;
            sincosf(psje, &sje, &cje);

            const float q  = vje2 / __ldg(v0p);
            const float q2 = q * q;
            const float am = __ldg(amaxp);
            const float afree = am * (1.0f - q2 * q2);

            float action = afree;
            const float sal = fbv - __ldg(lengths + jj);
            if (isfinite(sal)) {
                const float vl  = __ldg(st + fbx * 5 + 2);
                const float psl = __ldg(st + fbx * 5 + 3);
                float sl, cl;
                sincosf(psl, &sl, &cl);
                const float dvx = vl * cl - vje2 * cje;
                const float dvy = vl * sl - vje2 * sje;
                const float ndv = fmaf(dvx, cje, dvy * sje);

                const float sstar = __ldg(s0p) + vje2 * __ldg(dthp)
                                  + vje2 * ndv / (2.0f * sqrtf(am * __ldg(bp)));
                const float r = sstar / sal;
                action = afree - am * r * r;
            }
            out[(size_t)b * NV + jj] = action;
        }
    }
}

extern "C" void kernel_launch(void* const* d_in, const int* in_sizes, int n_in,
                              void* d_out, int out_size) {
    const float* state   = (const float*)d_in[0];
    const float* lengths = (const float*)d_in[1];
    const float* v0      = (const float*)d_in[2];
    const float* s0      = (const float*)d_in[3];
    const float* dth     = (const float*)d_in[4];
    const float* amax    = (const float*)d_in[5];
    const float* bpar    = (const float*)d_in[6];
    float* out = (float*)d_out;

    const int B = in_sizes[0] / (NV * 5);
    const int grid = B * BPB;    // 8 * 19 = 152 == #SMs on GB300
    idm_kernel<<<grid, THREADS>>>(state, lengths, v0, s0, dth, amax, bpar, out);
}